// round 1
// baseline (speedup 1.0000x reference)
#include <cuda_runtime.h>

// Problem dims
#define B_    32
#define CIN_  32
#define COUT_ 64
#define H_    128
#define W_    128
#define HO_   126
#define WO_   126
#define MAXCN_ 64

// Folded dense kernel: [COUT][CIN][3*3]
__device__ float g_kdense[COUT_ * CIN_ * 9];

__global__ void fold_kernel(const float* __restrict__ w, const int* __restrict__ cn) {
    int idx = blockIdx.x * blockDim.x + threadIdx.x;
    if (idx >= COUT_ * CIN_ * 9) return;
    int k = idx % 9;
    int c = (idx / 9) % CIN_;
    int o = idx / (9 * CIN_);
    int n = cn[o];
    float v = 0.f;
    if (c < n)        v += w[(o * MAXCN_ + c) * 9 + k];
    if (c + 32 < n)   v += w[(o * MAXCN_ + c + 32) * 9 + k];
    g_kdense[idx] = v;
}

#define SIN_STRIDE 72   // 10 rows x 72 (66 used); bank-conflict-free for compute reads

// Block: 512 threads = 8 oc-groups x 8 ho x 8 wo-lanes.
// Each thread: 8 output channels x 8 output columns (stride 8) x 1 row = 64 acc.
// Tile: all 64 oc x 8 ho x 64 wo for one batch image.
__global__ __launch_bounds__(512, 1)
void conv_kernel(const float* __restrict__ x,
                 const float* __restrict__ bias,
                 float* __restrict__ out) {
    __shared__ float sIn[10 * SIN_STRIDE];
    __shared__ float sW[COUT_ * 9];

    const int tid  = threadIdx.x;
    const int og   = tid >> 6;          // 0..7  (oc group of 8)
    const int ho_i = (tid >> 3) & 7;    // 0..7
    const int wo_g = tid & 7;           // 0..7

    const int wo0 = blockIdx.x * 64;    // 0 or 64
    const int ho0 = blockIdx.y * 8;     // 0..120
    const int b   = blockIdx.z;

    // ---- input staging slots (10*66 = 660 elems, 512 threads -> <=2 each) ----
    const int i0 = tid;
    const int i1 = tid + 512;
    const int r0 = i0 / 66, c0 = i0 % 66;
    const int r1 = i1 / 66, c1 = i1 % 66;
    const int row0 = ho0 + r0, col0 = wo0 + c0;
    const int row1 = ho0 + r1, col1 = wo0 + c1;
    const bool st1 = (i1 < 660);
    const bool v0  = (row0 < H_) && (col0 < W_);
    const bool v1  = st1 && (row1 < H_) && (col1 < W_);
    const int goff0 = row0 * W_ + col0;
    const int goff1 = row1 * W_ + col1;
    const float* xb = x + (long)b * CIN_ * H_ * W_;

    // ---- weight staging slots (64*9 = 576 elems) ----
    const int wi0 = tid;                 // always < 576? no: 512<576, ok
    const int wi1 = tid + 512;           // valid for tid<64
    const int woc0 = wi0 / 9, wk0 = wi0 % 9;
    const int woc1 = wi1 / 9, wk1 = wi1 % 9;
    const bool wv1 = (wi1 < 576);

    float acc[8][8];
    #pragma unroll
    for (int r = 0; r < 8; ++r)
        #pragma unroll
        for (int j = 0; j < 8; ++j) acc[r][j] = 0.f;

    // prefetch channel 0
    float pi0 = v0 ? __ldg(xb + goff0) : 0.f;
    float pi1 = v1 ? __ldg(xb + goff1) : 0.f;
    float pw0 = g_kdense[(woc0 * CIN_ + 0) * 9 + wk0];
    float pw1 = wv1 ? g_kdense[(woc1 * CIN_ + 0) * 9 + wk1] : 0.f;

    for (int c = 0; c < CIN_; ++c) {
        __syncthreads();   // prior compute finished reading smem
        sIn[r0 * SIN_STRIDE + c0] = pi0;
        if (st1) sIn[r1 * SIN_STRIDE + c1] = pi1;
        sW[wi0] = pw0;
        if (wv1) sW[wi1] = pw1;
        __syncthreads();   // staged data visible

        if (c < CIN_ - 1) {  // prefetch next channel; latency hidden by compute below
            const float* xc = xb + (long)(c + 1) * (H_ * W_);
            pi0 = v0 ? __ldg(xc + goff0) : 0.f;
            pi1 = v1 ? __ldg(xc + goff1) : 0.f;
            pw0 = g_kdense[(woc0 * CIN_ + (c + 1)) * 9 + wk0];
            if (wv1) pw1 = g_kdense[(woc1 * CIN_ + (c + 1)) * 9 + wk1];
        }

        // compute: 576 FMA / 144 LDS per channel per thread
        #pragma unroll
        for (int kh = 0; kh < 3; ++kh) {
            const float* rowp = &sIn[(ho_i + kh) * SIN_STRIDE + wo_g];
            float wr[8][3];
            #pragma unroll
            for (int r = 0; r < 8; ++r) {
                #pragma unroll
                for (int kw = 0; kw < 3; ++kw)
                    wr[r][kw] = sW[(og * 8 + r) * 9 + kh * 3 + kw];  // warp-broadcast
            }
            #pragma unroll
            for (int j = 0; j < 8; ++j) {
                float a0 = rowp[8 * j];
                float a1 = rowp[8 * j + 1];
                float a2 = rowp[8 * j + 2];
                #pragma unroll
                for (int r = 0; r < 8; ++r) {
                    float t = acc[r][j];
                    t = fmaf(wr[r][0], a0, t);
                    t = fmaf(wr[r][1], a1, t);
                    t = fmaf(wr[r][2], a2, t);
                    acc[r][j] = t;
                }
            }
        }
    }

    // epilogue: add bias, store (coalesced: lanes wo_g are consecutive columns)
    const int ho = ho0 + ho_i;
    if (ho < HO_) {
        #pragma unroll
        for (int r = 0; r < 8; ++r) {
            const int oc = og * 8 + r;
            const float* bp = bias + ((long)oc * HO_ + ho) * WO_;
            float* op = out + (((long)b * COUT_ + oc) * HO_ + ho) * WO_;
            #pragma unroll
            for (int j = 0; j < 8; ++j) {
                const int wo = wo0 + wo_g + 8 * j;
                if (wo < WO_) op[wo] = acc[r][j] + __ldg(bp + wo);
            }
        }
    }
}

extern "C" void kernel_launch(void* const* d_in, const int* in_sizes, int n_in,
                              void* d_out, int out_size) {
    const float* x    = (const float*)d_in[0];   // [32,32,128,128]
    const float* w    = (const float*)d_in[1];   // [64,64,3,3]
    const float* bias = (const float*)d_in[2];   // [64,126,126]
    const int*   cn   = (const int*)d_in[3];     // [64]
    float* out = (float*)d_out;                  // [32,64,126,126]

    fold_kernel<<<(COUT_ * CIN_ * 9 + 255) / 256, 256>>>(w, cn);
    conv_kernel<<<dim3(2, 16, 32), 512>>>(x, bias, out);
}